// round 9
// baseline (speedup 1.0000x reference)
#include <cuda_runtime.h>
#include <cuda_bf16.h>

#define BB 4
#define SS 2048
#define HH 2048
#define RR 64
#define KSPLIT 4
#define KPER (2048 / KSPLIT)   // 512 per CTA
#define NC (KPER / 32)         // 16 k-chunks of 32

// ---------------------------------------------------------------------------
// Global scratch (static device arrays; no runtime allocation).
// ---------------------------------------------------------------------------
__device__ __align__(16) unsigned short g_Wsh[RR * SS];
__device__ __align__(16) unsigned short g_Wsl[RR * SS];
__device__ __align__(16) unsigned short g_Whh[RR * HH];
__device__ __align__(16) unsigned short g_Whl[RR * HH];
__device__ __align__(16) unsigned short g_Fsh[BB * SS * RR];  // F_s [b][s][r]
__device__ __align__(16) unsigned short g_Fsl[BB * SS * RR];
__device__ __align__(16) unsigned short g_Fhh[BB * HH * RR];  // F_h [b][h][r]
__device__ __align__(16) unsigned short g_Fhl[BB * HH * RR];
// split-K fp32 partials: [gb(8)][tile(16)][ky(4)][128*64]  (16.8 MB)
__device__ __align__(16) float g_part[8 * 16 * KSPLIT * 128 * 64];

// ---------------------------------------------------------------------------
// Helpers
// ---------------------------------------------------------------------------
__device__ __forceinline__ unsigned pack2(float v0, float v1) {
    __nv_bfloat162 t = __floats2bfloat162_rn(v0, v1);
    return *reinterpret_cast<unsigned*>(&t);
}

__device__ __forceinline__ void split_pair(float v0, float v1, unsigned& h, unsigned& l) {
    h = pack2(v0, v1);
    float h0 = __uint_as_float(h << 16);
    float h1 = __uint_as_float(h & 0xFFFF0000u);
    l = pack2(v0 - h0, v1 - h1);
}

__device__ __forceinline__ void mma_bf16(float c[4], const unsigned a[4], const unsigned b[2]) {
    asm volatile(
        "mma.sync.aligned.m16n8k16.row.col.f32.bf16.bf16.f32 "
        "{%0,%1,%2,%3}, {%4,%5,%6,%7}, {%8,%9}, {%0,%1,%2,%3};\n"
        : "+f"(c[0]), "+f"(c[1]), "+f"(c[2]), "+f"(c[3])
        : "r"(a[0]), "r"(a[1]), "r"(a[2]), "r"(a[3]), "r"(b[0]), "r"(b[1]));
}

__device__ __forceinline__ void ldsm4(unsigned* r, unsigned a) {
    asm volatile("ldmatrix.sync.aligned.m8n8.x4.shared.b16 {%0,%1,%2,%3}, [%4];\n"
                 : "=r"(r[0]), "=r"(r[1]), "=r"(r[2]), "=r"(r[3]) : "r"(a));
}
__device__ __forceinline__ void ldsm4t(unsigned* r, unsigned a) {
    asm volatile("ldmatrix.sync.aligned.m8n8.x4.trans.shared.b16 {%0,%1,%2,%3}, [%4];\n"
                 : "=r"(r[0]), "=r"(r[1]), "=r"(r[2]), "=r"(r[3]) : "r"(a));
}

__device__ __forceinline__ void cp16(unsigned dst, const void* src) {
    asm volatile("cp.async.cg.shared.global [%0], [%1], 16;\n" :: "r"(dst), "l"(src));
}
__device__ __forceinline__ void cp_commit() { asm volatile("cp.async.commit_group;\n"); }
__device__ __forceinline__ void cp_wait1()  { asm volatile("cp.async.wait_group 1;\n" ::: "memory"); }
__device__ __forceinline__ void cp_wait0()  { asm volatile("cp.async.wait_group 0;\n" ::: "memory"); }

// ---------------------------------------------------------------------------
// Kernel 0: split the two small W matrices fp32 -> hi/lo bf16.
// blocks [0,64): Wseq, [64,128): Whid. Each RR*2048 floats.
// ---------------------------------------------------------------------------
__global__ void __launch_bounds__(256) wsplit_kernel(const float4* __restrict__ Wseq,
                                                     const float4* __restrict__ Whid) {
    const bool second = blockIdx.x >= 64;
    const float4* src = second ? Whid : Wseq;
    uint2* dh = (uint2*)(second ? g_Whh : g_Wsh);
    uint2* dl = (uint2*)(second ? g_Whl : g_Wsl);
    const int n4 = RR * SS / 4;
    for (int i = (blockIdx.x & 63) * 256 + threadIdx.x; i < n4; i += 64 * 256) {
        float4 v = src[i];
        unsigned h0, l0, h1, l1;
        split_pair(v.x, v.y, h0, l0);
        split_pair(v.z, v.w, h1, l1);
        dh[i] = make_uint2(h0, h1);
        dl[i] = make_uint2(l0, l1);
    }
}

// ---------------------------------------------------------------------------
// Kernel 1: fused factor GEMMs, split-K, fused fp32->bf16 split of X.
//   x in [0,16):  G1: F_s rows = X_b[m0:+128, :] @ Whid^T      A=[m][k] (ldsm)
//   x in [16,32): G2: F_h rows = (X_b[:, h0:+128])^T @ Wseq^T  A=[k][m] (ldsm.trans)
// A: LDG.128 fp32 X -> register split -> STS bf16 hi/lo (double-buffered smem).
// B: pre-split W via cp.async. One __syncthreads per k-chunk.
// M tile 128, N=64, K chunk 32. 8 warps, warp tile 32x32.
// ---------------------------------------------------------------------------
#define AP1 40     // G1 A pitch (shorts): [m=128][k=32]
#define AP2 136    // G2 A pitch (shorts): [k=32][m=128]
#define BP  40     // B pitch: [n=64][k=32]
#define ABUF 5120                        // shorts per A sub-buffer
#define BBUF 2560                        // shorts per B sub-buffer
#define STG  (2 * ABUF + 2 * BBUF)       // 15360 shorts per stage
#define FSM_BYTES (2 * STG * 2)          // 61440 bytes (2 stages)

__global__ void __launch_bounds__(256, 2) fact_kernel(const float* __restrict__ X) {
    extern __shared__ unsigned short fsm[];
    const unsigned sbase = (unsigned)__cvta_generic_to_shared(fsm);

    const int b = blockIdx.z, ky = blockIdx.y, tid = threadIdx.x;
    const bool isG1 = (blockIdx.x < 16);
    const int tile = isG1 ? blockIdx.x : blockIdx.x - 16;
    const int m0 = tile * 128;
    const int kbase = ky * KPER;

    // ---- A source pointers (fp32 X), 4 x float4 per thread per chunk ----
    const float* pA[4];
    long astep;
    int sr[4], sc[4];  // smem (row, col) per p
    if (isG1) {
#pragma unroll
        for (int p = 0; p < 4; ++p) {
            int idx = tid + p * 256;
            int row = idx >> 3, c4 = (idx & 7) * 4;
            pA[p] = X + ((long)(b * SS + m0 + row)) * HH + kbase + c4;
            sr[p] = row; sc[p] = c4;
        }
        astep = 32;
    } else {
#pragma unroll
        for (int p = 0; p < 4; ++p) {
            int idx = tid + p * 256;
            int kr = idx >> 5, c4 = (idx & 31) * 4;
            pA[p] = X + ((long)(b * SS + kbase + kr)) * HH + m0 + c4;
            sr[p] = kr; sc[p] = c4;
        }
        astep = (long)32 * HH;
    }
    const int APx = isG1 ? AP1 : AP2;

    // ---- B staging (cp.async): 64 n-rows x 32 k, hi+lo ----
    const unsigned short* Bh_src = isG1 ? g_Whh : g_Wsh;
    const unsigned short* Bl_src = isG1 ? g_Whl : g_Wsl;
    const int brow = tid >> 2, bc = (tid & 3) * 8;
    const long bsoff = (long)brow * (isG1 ? HH : SS) + kbase + bc;
    const unsigned bdst = (unsigned)((2 * ABUF + brow * BP + bc) * 2);

    auto issueB = [&](int kc, int s) {
        const unsigned base = sbase + (unsigned)(s * STG * 2) + bdst;
        const long off = bsoff + kc * 32;
        cp16(base, Bh_src + off);
        cp16(base + BBUF * 2, Bl_src + off);
    };

    float4 pa[4];
#pragma unroll
    for (int p = 0; p < 4; ++p) pa[p] = *(const float4*)pA[p];
    issueB(0, 0); cp_commit();

    const int warpId = tid >> 5, lane = tid & 31;
    const int mB = (warpId >> 1) * 32, nB = (warpId & 1) * 32;

    const unsigned aoff1 = (unsigned)(((mB + (lane & 15)) * AP1 + (lane >> 4) * 8) * 2);
    const unsigned aoff2 = (unsigned)(((((lane & 7) + ((lane & 16) >> 1)) * AP2) +
                                       mB + ((lane >> 3) & 1) * 8) * 2);
    const unsigned boff  = (unsigned)(((nB + (lane & 7) + ((lane & 16) >> 1)) * BP +
                                       (lane & 8)) * 2);

    float acc[2][4][4];
#pragma unroll
    for (int i = 0; i < 2; ++i)
#pragma unroll
        for (int j = 0; j < 4; ++j)
#pragma unroll
            for (int t = 0; t < 4; ++t) acc[i][j][t] = 0.0f;

#pragma unroll 1
    for (int kc = 0; kc < NC; ++kc) {
        const unsigned base = sbase + (unsigned)((kc & 1) * STG * 2);
        const unsigned bAh = base, bAl = base + ABUF * 2;
        const unsigned bBh = base + 2 * ABUF * 2, bBl = bBh + BBUF * 2;

        // split prefetched A regs -> smem stage kc&1 (readers drained 2 syncs ago)
        unsigned short* Ahp = fsm + (kc & 1) * STG;
        unsigned short* Alp = Ahp + ABUF;
#pragma unroll
        for (int p = 0; p < 4; ++p) {
            unsigned h0, l0, h1, l1;
            split_pair(pa[p].x, pa[p].y, h0, l0);
            split_pair(pa[p].z, pa[p].w, h1, l1);
            int o = sr[p] * APx + sc[p];
            *(uint2*)&Ahp[o] = make_uint2(h0, h1);
            *(uint2*)&Alp[o] = make_uint2(l0, l1);
        }
        cp_wait0();        // B(kc) landed (issued before previous sync)
        __syncthreads();   // publishes A stage kc&1; retires readers of stage (kc+1)&1

        if (kc + 1 < NC) {
            issueB(kc + 1, (kc + 1) & 1); cp_commit();
#pragma unroll
            for (int p = 0; p < 4; ++p) {
                pA[p] += astep;
                pa[p] = *(const float4*)pA[p];
            }
        }

#pragma unroll
        for (int kb = 0; kb < 32; kb += 16) {
            unsigned bhf[2][4], blf[2][4];
            ldsm4(bhf[0], bBh + boff + kb * 2);
            ldsm4(bhf[1], bBh + boff + kb * 2 + 16 * BP * 2);
            ldsm4(blf[0], bBl + boff + kb * 2);
            ldsm4(blf[1], bBl + boff + kb * 2 + 16 * BP * 2);
#pragma unroll
            for (int i = 0; i < 2; ++i) {
                unsigned ah[4], al[4];
                if (isG1) {
                    unsigned o = aoff1 + (unsigned)(i * 16 * AP1 * 2 + kb * 2);
                    ldsm4(ah, bAh + o);
                    ldsm4(al, bAl + o);
                } else {
                    unsigned o = aoff2 + (unsigned)(kb * AP2 * 2 + i * 16 * 2);
                    ldsm4t(ah, bAh + o);
                    ldsm4t(al, bAl + o);
                }
#pragma unroll
                for (int j = 0; j < 4; ++j) {
                    const unsigned* bhp = &bhf[j >> 1][(j & 1) * 2];
                    const unsigned* blp = &blf[j >> 1][(j & 1) * 2];
                    mma_bf16(acc[i][j], ah, bhp);
                    mma_bf16(acc[i][j], ah, blp);
                    mma_bf16(acc[i][j], al, bhp);
                }
            }
        }
    }

    // epilogue: fp32 partial tile (128x64) -> g_part
    const int g = lane >> 2, q = lane & 3;
    const int gb = b * 2 + (isG1 ? 0 : 1);
    float* P = g_part + ((long)((gb * 16 + tile) * KSPLIT + ky)) * (128 * 64);
#pragma unroll
    for (int i = 0; i < 2; ++i)
#pragma unroll
        for (int j = 0; j < 4; ++j) {
            int r0 = mB + i * 16 + g;
            int c  = nB + j * 8 + 2 * q;
            *(float2*)&P[r0 * 64 + c]       = make_float2(acc[i][j][0], acc[i][j][1]);
            *(float2*)&P[(r0 + 8) * 64 + c] = make_float2(acc[i][j][2], acc[i][j][3]);
        }
}

// ---------------------------------------------------------------------------
// Kernel 1b: reduce split-K partials, split fp32 -> hi/lo bf16 factors.
// ---------------------------------------------------------------------------
__global__ void __launch_bounds__(256) reduce_kernel() {
    const int t  = blockIdx.x * 256 + threadIdx.x;   // 0 .. 262143
    const int t4 = t << 2;
    const int n    = t4 & 63;
    const int m    = (t4 >> 6) & 127;
    const int tile = (t4 >> 13) & 15;
    const int gb   = t4 >> 17;            // b*2 + gemm
    const int b    = gb >> 1;
    const int gemm = gb & 1;

    const float4* P = (const float4*)g_part +
                      ((long)(gb * 16 + tile) * KSPLIT * (128 * 64) + (m * 64 + n)) / 4;
    float4 s = P[0];
#pragma unroll
    for (int k = 1; k < KSPLIT; ++k) {
        float4 v = P[k * (128 * 64 / 4)];
        s.x += v.x; s.y += v.y; s.z += v.z; s.w += v.w;
    }

    unsigned h0, l0, h1, l1;
    split_pair(s.x, s.y, h0, l0);
    split_pair(s.z, s.w, h1, l1);

    const long base = ((long)b * SS + tile * 128 + m) * RR + n;  // SS == HH
    unsigned short* oh = gemm == 0 ? g_Fsh : g_Fhh;
    unsigned short* ol = gemm == 0 ? g_Fsl : g_Fhl;
    *(uint2*)&oh[base] = make_uint2(h0, h1);
    *(uint2*)&ol[base] = make_uint2(l0, l1);
}

// ---------------------------------------------------------------------------
// Kernel 2: Out_b = F_s[b] (S x 64) @ F_h[b]^T (64 x H), fp32 out.
// CTA: A = F_s tile (128 x 64) resident; loops over OTILES=4 h-tiles with
// cp.async double-buffered B. grid (4, 16, 4) = 256 CTAs = one wave @ 2/SM.
// 8 warps, warp tile 64x32.
// ---------------------------------------------------------------------------
#define OTILES 4
#define OAP 72
#define OBUF (128 * OAP)                 // shorts per sub-buffer
#define OBUF_B (OBUF * 2)                // bytes per sub-buffer (18432)
#define OSM_TOT_BYTES (6 * OBUF_B)       // A(hi,lo) + 2 x B(hi,lo) = 110592

__global__ void __launch_bounds__(256, 2) out_kernel(float* __restrict__ Out) {
    extern __shared__ unsigned short sm[];
    const unsigned sbase = (unsigned)__cvta_generic_to_shared(sm);

    const int b = blockIdx.z, s0 = blockIdx.y * 128, hg = blockIdx.x * OTILES;
    const int tid = threadIdx.x;

    // staging map: 4 x 16B chunks per sub-buffer per thread (128 rows x 64 k)
    const int crow = tid >> 1;                 // base rows: 2 chunks/row
    const int ccol = (tid & 1) * 8;

    auto stageA = [&]() {
        const unsigned short* gh = g_Fsh + ((long)(b * SS + s0)) * RR;
        const unsigned short* gl = g_Fsl + ((long)(b * SS + s0)) * RR;
#pragma unroll
        for (int p = 0; p < 4; ++p) {
            int r = crow, c = ccol + (p & 1) * 16;
            if (p >= 2) r = 0;                 // placeholder, recomputed below
            int idx = tid + p * 256;
            r = idx >> 3; c = (idx & 7) * 8;
            unsigned d = sbase + (unsigned)((r * OAP + c) * 2);
            cp16(d, gh + r * RR + c);
            cp16(d + OBUF_B, gl + r * RR + c);
        }
    };
    auto stageB = [&](int ht, int s) {
        const unsigned short* gh = g_Fhh + ((long)(b * HH + ht * 128)) * RR;
        const unsigned short* gl = g_Fhl + ((long)(b * HH + ht * 128)) * RR;
        const unsigned base = sbase + (unsigned)((2 + 2 * s) * OBUF_B);
#pragma unroll
        for (int p = 0; p < 4; ++p) {
            int idx = tid + p * 256;
            int r = idx >> 3, c = (idx & 7) * 8;
            unsigned d = base + (unsigned)((r * OAP + c) * 2);
            cp16(d, gh + r * RR + c);
            cp16(d + OBUF_B, gl + r * RR + c);
        }
    };

    stageA(); stageB(hg + 0, 0); cp_commit();   // group 0
    stageB(hg + 1, 1); cp_commit();             // group 1

    const int warpId = tid >> 5, lane = tid & 31;
    const int mB = (warpId >> 2) * 64, nB = (warpId & 3) * 32;
    const int g = lane >> 2, q = lane & 3;

    const unsigned aoff = 2 * ((mB + (lane & 15)) * OAP + (lane >> 4) * 8);
    const unsigned aH = sbase + aoff, aL = sbase + OBUF_B + aoff;
    const unsigned boff = 2 * ((nB + (lane & 7) + ((lane & 16) >> 1)) * OAP + (lane & 8));

#pragma unroll 1
    for (int j = 0; j < OTILES; ++j) {
        if (j < OTILES - 1) cp_wait1(); else cp_wait0();
        __syncthreads();   // B(j) visible; also fences prior-tile readers

        const unsigned bB = sbase + (unsigned)((2 + 2 * (j & 1)) * OBUF_B);
        const unsigned bH = bB + boff, bL = bB + OBUF_B + boff;

        float acc[4][4][4];
#pragma unroll
        for (int i = 0; i < 4; ++i)
#pragma unroll
            for (int jj = 0; jj < 4; ++jj)
#pragma unroll
                for (int t = 0; t < 4; ++t) acc[i][jj][t] = 0.0f;

#pragma unroll
        for (int kb = 0; kb < 64; kb += 16) {
            unsigned bhf[2][4], blf[2][4];
            ldsm4(bhf[0], bH + kb * 2);
            ldsm4(bhf[1], bH + kb * 2 + 16 * OAP * 2);
            ldsm4(blf[0], bL + kb * 2);
            ldsm4(blf[1], bL + kb * 2 + 16 * OAP * 2);
#pragma unroll
            for (int i = 0; i < 4; ++i) {
                unsigned ah[4], al[4];
                ldsm4(ah, aH + kb * 2 + i * (16 * OAP * 2));
                ldsm4(al, aL + kb * 2 + i * (16 * OAP * 2));
#pragma unroll
                for (int jj = 0; jj < 4; ++jj) {
                    const unsigned* bhp = &bhf[jj >> 1][(jj & 1) * 2];
                    const unsigned* blp = &blf[jj >> 1][(jj & 1) * 2];
                    mma_bf16(acc[i][jj], ah, bhp);
                    mma_bf16(acc[i][jj], ah, blp);
                    mma_bf16(acc[i][jj], al, bhp);
                }
            }
        }

        // store tile j
        float* O = Out + ((long)(b * SS + s0)) * HH + (hg + j) * 128;
#pragma unroll
        for (int i = 0; i < 4; ++i)
#pragma unroll
            for (int jj = 0; jj < 4; ++jj) {
                int r = mB + i * 16 + g;
                int c = nB + jj * 8 + 2 * q;
                *(float2*)&O[(long)r * HH + c]       = make_float2(acc[i][jj][0], acc[i][jj][1]);
                *(float2*)&O[(long)(r + 8) * HH + c] = make_float2(acc[i][jj][2], acc[i][jj][3]);
            }

        if (j + 2 < OTILES) {
            __syncthreads();                    // readers of buf (j&1) done
            stageB(hg + j + 2, j & 1); cp_commit();
        }
    }
}

// ---------------------------------------------------------------------------
// Launch: inputs per metadata: hidden_states, grid_chw (unused), W_seq, W_hid
// ---------------------------------------------------------------------------
extern "C" void kernel_launch(void* const* d_in, const int* in_sizes, int n_in,
                              void* d_out, int out_size) {
    const float* X    = (const float*)d_in[0];
    const float* Wseq = (const float*)d_in[2];
    const float* Whid = (const float*)d_in[3];
    float* Out = (float*)d_out;

    cudaFuncSetAttribute(fact_kernel, cudaFuncAttributeMaxDynamicSharedMemorySize,
                         FSM_BYTES);
    cudaFuncSetAttribute(out_kernel, cudaFuncAttributeMaxDynamicSharedMemorySize,
                         OSM_TOT_BYTES);

    wsplit_kernel<<<128, 256>>>((const float4*)Wseq, (const float4*)Whid);
    fact_kernel<<<dim3(32, KSPLIT, BB), 256, FSM_BYTES>>>(X);
    reduce_kernel<<<1024, 256>>>();
    out_kernel<<<dim3(HH / 128 / OTILES, SS / 128, BB), 256, OSM_TOT_BYTES>>>(Out);
}